// round 12
// baseline (speedup 1.0000x reference)
#include <cuda_runtime.h>
#include <cuda_fp16.h>
#include <math.h>
#include <stdint.h>

// Problem constants
#define BATCH 2
#define SEQ   2048
#define DMODEL 2048
#define NHEAD 16
#define HDIM  128
#define MROWS (BATCH*SEQ)          // 4096
#define WINDOW 512
#define SCALE_F 0.08838834764831845f   // 1/sqrt(128)
#define QKV_ST (3*DMODEL)          // fused QKV row stride
// exp(s*SCALE - 3) via ex2: C1 = SCALE*log2e, C2 = -3*log2e
#define EXP_C1 0.12754334f
#define EXP_C2 (-4.32808512f)

// Scratch (device globals; no allocation allowed)
__device__ __align__(16) __half g_QKVh[ (size_t)MROWS * QKV_ST ];
__device__ __align__(16) __half g_AOh [ (size_t)MROWS * DMODEL ];
__device__ __align__(16) __half g_xh  [ (size_t)MROWS * DMODEL ];
__device__ __align__(16) __half g_Wh  [ (size_t)4 * DMODEL * DMODEL ];

// ---------------------------------------------------------------------------
// helpers
// ---------------------------------------------------------------------------
__device__ __forceinline__ uint32_t smem_u32(const void* p) {
    uint32_t a;
    asm("{ .reg .u64 t; cvta.to.shared.u64 t, %1; cvt.u32.u64 %0, t; }" : "=r"(a) : "l"(p));
    return a;
}

__device__ __forceinline__ void cp_async16(uint32_t dst, const void* src) {
    size_t g = __cvta_generic_to_global(src);
    asm volatile("cp.async.cg.shared.global [%0], [%1], 16;\n" :: "r"(dst), "l"(g));
}
#define CP_COMMIT() asm volatile("cp.async.commit_group;\n" ::: "memory")
#define CP_WAIT(n)  asm volatile("cp.async.wait_group %0;\n" :: "n"(n) : "memory")

__device__ __forceinline__ float ex2f(float x) {
    float r;
    asm("ex2.approx.ftz.f32 %0, %1;" : "=f"(r) : "f"(x));
    return r;
}

// fp16 mma m16n8k16, fp32 accumulate
__device__ __forceinline__ void mma16(float* c, const uint32_t* a, const uint32_t* b) {
    asm volatile(
        "mma.sync.aligned.m16n8k16.row.col.f32.f16.f16.f32 "
        "{%0,%1,%2,%3}, {%4,%5,%6,%7}, {%8,%9}, {%0,%1,%2,%3};"
        : "+f"(c[0]), "+f"(c[1]), "+f"(c[2]), "+f"(c[3])
        : "r"(a[0]), "r"(a[1]), "r"(a[2]), "r"(a[3]), "r"(b[0]), "r"(b[1]));
}

__device__ __forceinline__ uint32_t h2u(float x, float y) {
    __half2 h = __floats2half2_rn(x, y);
    return *(uint32_t*)&h;
}

__device__ __forceinline__ void ldm_x4(uint32_t* r, uint32_t addr) {
    asm volatile("ldmatrix.sync.aligned.m8n8.x4.shared.b16 {%0,%1,%2,%3}, [%4];"
        : "=r"(r[0]), "=r"(r[1]), "=r"(r[2]), "=r"(r[3]) : "r"(addr));
}
__device__ __forceinline__ void ldm_x4_trans(uint32_t* r, uint32_t addr) {
    asm volatile("ldmatrix.sync.aligned.m8n8.x4.trans.shared.b16 {%0,%1,%2,%3}, [%4];"
        : "=r"(r[0]), "=r"(r[1]), "=r"(r[2]), "=r"(r[3]) : "r"(addr));
}

__device__ __forceinline__ void store2(float* C, size_t idx, float a, float b) {
    *(float2*)&C[idx] = make_float2(a, b);
}
__device__ __forceinline__ void store2(__half* C, size_t idx, float a, float b) {
    *(__half2*)&C[idx] = __floats2half2_rn(a, b);
}

// ---------------------------------------------------------------------------
// float -> half conversion: 8 floats in / uint4 out per thread
// ---------------------------------------------------------------------------
__global__ __launch_bounds__(256)
void cvt_f16_kernel(const float4* __restrict__ in, uint4* __restrict__ out, int n8) {
    int i = blockIdx.x * blockDim.x + threadIdx.x;
    if (i < n8) {
        float4 v0 = in[2 * i], v1 = in[2 * i + 1];
        uint4 o;
        o.x = h2u(v0.x, v0.y); o.y = h2u(v0.z, v0.w);
        o.z = h2u(v1.x, v1.y); o.w = h2u(v1.z, v1.w);
        out[i] = o;
    }
}

__global__ __launch_bounds__(256)
void cvt_w4_kernel(const float* __restrict__ w0, const float* __restrict__ w1,
                   const float* __restrict__ w2, const float* __restrict__ w3,
                   __half* __restrict__ out, int n8each) {
    int i = blockIdx.x * blockDim.x + threadIdx.x;
    int sel = i / n8each;
    int idx = i - sel * n8each;
    const float4* src = (const float4*)((sel == 0) ? w0 : (sel == 1) ? w1 : (sel == 2) ? w2 : w3);
    float4 v0 = src[2 * idx], v1 = src[2 * idx + 1];
    uint4 o;
    o.x = h2u(v0.x, v0.y); o.y = h2u(v0.z, v0.w);
    o.z = h2u(v1.x, v1.y); o.w = h2u(v1.z, v1.w);
    ((uint4*)(out + (size_t)sel * (8 * (size_t)n8each)))[idx] = o;
}

// ---------------------------------------------------------------------------
// fp16 GEMM: C[M,N] = A[M,K](f16) * Bw[N,K](f16)^T, fp32 accum, OutT output.
// Block 128x128, BK=64 halves, 3-stage cp.async, 2 CTAs/SM (16 warps resident).
// 8 warps 2x4, warp tile 64x32.
// ---------------------------------------------------------------------------
#define BM 128
#define BN 128
#define BKH 64
#define NSTAGE 3
#define A_BYTES (BM*128)                  // 16384
#define STG_BY ((BM+BN)*128)              // 32768
#define GEMM_SMEM (NSTAGE*STG_BY + 1024)  // 99328

template <typename TO>
__global__ __launch_bounds__(256, 2)
void gemm_h(const __half* __restrict__ A, const __half* __restrict__ Bw,
            TO* __restrict__ C, int M, int N, int K) {
    constexpr int WN = 32;                 // warp n-span
    constexpr int NT = 4;                  // n8 tiles per warp
    constexpr int NB = 2;                  // B ldmatrix.x4 per kk

    extern __shared__ char dsm[];
    const int tid  = threadIdx.x;
    const int lane = tid & 31;
    const int warp = tid >> 5;
    const int m0 = blockIdx.y * BM;
    const int n0 = blockIdx.x * BN;
    const int NIT = K / BKH;

    const uint32_t sbase = (smem_u32(dsm) + 1023) & ~1023u;

    auto fill = [&](int it) {
        uint32_t st = sbase + (it % NSTAGE) * STG_BY;
        size_t kb = (size_t)it * BKH;
#pragma unroll
        for (int i = 0; i < 4; i++) {
            int id = tid + i * 256;
            int row = id >> 3, c = id & 7;
            uint32_t off = (uint32_t)(row * 128 + c * 16);
            cp_async16(st + (off ^ ((off >> 3) & 0x70)),
                       A + (size_t)(m0 + row) * K + kb + c * 8);
        }
        uint32_t stB = st + A_BYTES;
#pragma unroll
        for (int i = 0; i < 4; i++) {
            int id = tid + i * 256;
            int row = id >> 3, c = id & 7;
            uint32_t off = (uint32_t)(row * 128 + c * 16);
            cp_async16(stB + (off ^ ((off >> 3) & 0x70)),
                       Bw + (size_t)(n0 + row) * K + kb + c * 8);
        }
        CP_COMMIT();
    };

    float acc[4][NT][4];
#pragma unroll
    for (int mt = 0; mt < 4; mt++)
#pragma unroll
        for (int nt = 0; nt < NT; nt++)
#pragma unroll
            for (int r = 0; r < 4; r++) acc[mt][nt][r] = 0.f;

    fill(0);
    fill(1);

    const int wm = (warp & 1) * 64;
    const int wn = (warp >> 1) * WN;
    const int a_row  = lane & 15;
    const int a_koff = (lane >> 4) * 8;
    const int b_row  = ((lane >> 4) << 3) + (lane & 7);
    const int b_koff = ((lane >> 3) & 1) * 8;

    for (int j = 0; j < NIT; j++) {
        CP_WAIT(1);
        __syncthreads();
        if (j + 2 < NIT) fill(j + 2);

        uint32_t st = sbase + (j % NSTAGE) * STG_BY;
#pragma unroll
        for (int kk = 0; kk < BKH; kk += 16) {
            uint32_t a[4][4], b[NT][2];
#pragma unroll
            for (int mt = 0; mt < 4; mt++) {
                uint32_t off = (uint32_t)((wm + mt * 16 + a_row) * 128 + (kk + a_koff) * 2);
                ldm_x4(a[mt], st + (off ^ ((off >> 3) & 0x70)));
            }
#pragma unroll
            for (int np = 0; np < NB; np++) {
                uint32_t off = (uint32_t)((wn + np * 16 + b_row) * 128 + (kk + b_koff) * 2);
                uint32_t r4[4];
                ldm_x4(r4, st + A_BYTES + (off ^ ((off >> 3) & 0x70)));
                b[np * 2][0] = r4[0]; b[np * 2][1] = r4[1];
                b[np * 2 + 1][0] = r4[2]; b[np * 2 + 1][1] = r4[3];
            }
#pragma unroll
            for (int mt = 0; mt < 4; mt++)
#pragma unroll
                for (int nt = 0; nt < NT; nt++)
                    mma16(acc[mt][nt], a[mt], b[nt]);
        }
    }

#pragma unroll
    for (int mt = 0; mt < 4; mt++)
#pragma unroll
        for (int nt = 0; nt < NT; nt++) {
            int row = m0 + wm + mt * 16 + (lane >> 2);
            int col = n0 + wn + nt * 8 + (lane & 3) * 2;
            store2(C, (size_t)row * N + col,       acc[mt][nt][0], acc[mt][nt][1]);
            store2(C, (size_t)(row + 8) * N + col, acc[mt][nt][2], acc[mt][nt][3]);
        }
}

// ---------------------------------------------------------------------------
// Windowed flash attention, fp16 mma + ldmatrix (unchanged from R11).
// ---------------------------------------------------------------------------
#define QST 136
#define KST 136
#define SMQ (128 * QST)
#define SMKV (64 * KST)
#define ATTN_SMEM_BYTES ((SMQ + 4 * SMKV) * 2)   // 104448 B

__global__ __launch_bounds__(256, 2)
void attn_h(const __half* __restrict__ QKV, __half* __restrict__ O) {
    extern __shared__ __half hsm[];
    __half* Qs = hsm;
    __half* Ks = hsm + SMQ;
    __half* Vs = hsm + SMQ + 2 * SMKV;

    const int tid  = threadIdx.x;
    const int lane = tid & 31;
    const int warp = tid >> 5;
    const int qt = blockIdx.x, h = blockIdx.y, b = blockIdx.z;
    const int q0 = qt * 128;

    const uint32_t sQ = smem_u32(Qs);
    const uint32_t sK = smem_u32(Ks);
    const uint32_t sV = smem_u32(Vs);

    const int jmin = (q0 > (WINDOW - 1)) ? (q0 - (WINDOW - 1)) : 0;
    const int t0 = jmin >> 6;
    const int t1 = (q0 + 127) >> 6;

    auto fillKV = [&](int kt) {
        int buf = kt & 1;
        const __half* Kb = QKV + ((size_t)(b * SEQ + kt * 64)) * QKV_ST + DMODEL + h * HDIM;
        const __half* Vb = Kb + DMODEL;
#pragma unroll
        for (int i = 0; i < 4; i++) {
            int id = tid + i * 256;
            int row = id >> 4, c = id & 15;
            uint32_t doff = (uint32_t)(buf * SMKV + row * KST + c * 8) * 2;
            cp_async16(sK + doff, Kb + (size_t)row * QKV_ST + c * 8);
            cp_async16(sV + doff, Vb + (size_t)row * QKV_ST + c * 8);
        }
        CP_COMMIT();
    };

    {
        const __half* Qb = QKV + ((size_t)(b * SEQ + q0)) * QKV_ST + h * HDIM;
#pragma unroll
        for (int i = 0; i < 8; i++) {
            int id = tid + i * 256;
            int row = id >> 4, c = id & 15;
            cp_async16(sQ + (uint32_t)(row * QST + c * 8) * 2,
                       Qb + (size_t)row * QKV_ST + c * 8);
        }
    }
    fillKV(t0);

    float o[16][4];
#pragma unroll
    for (int nt = 0; nt < 16; nt++)
#pragma unroll
        for (int r = 0; r < 4; r++) o[nt][r] = 0.f;
    float l0 = 0.f, l1 = 0.f;

    const int qrow  = q0 + warp * 16 + (lane >> 2);
    const int i_min = q0 + warp * 16;
    const int i_max = i_min + 15;
    const int a_row  = warp * 16 + (lane & 15);
    const int a_koff = (lane >> 4) * 8;
    const int b_row  = ((lane >> 4) << 3) + (lane & 7);
    const int b_koff = ((lane >> 3) & 1) * 8;
    const int v_krow = lane & 15;
    const int v_noff = (lane >> 4) * 8;

    for (int kt = t0; kt <= t1; kt++) {
        const int j0 = kt * 64;
        const int buf = kt & 1;
        CP_WAIT(0);
        __syncthreads();
        if (kt < t1) fillKV(kt + 1);

        const bool dead = (j0 > i_max) || (j0 + 63 + (WINDOW - 1) < i_min);
        if (dead) continue;
        const bool need_mask = (j0 + 63 > i_min) || (j0 < i_max - (WINDOW - 1));

        const uint32_t sKb = sK + (uint32_t)(buf * SMKV) * 2;
        const uint32_t sVb = sV + (uint32_t)(buf * SMKV) * 2;

        float s[8][4];
#pragma unroll
        for (int nt = 0; nt < 8; nt++)
#pragma unroll
            for (int r = 0; r < 4; r++) s[nt][r] = 0.f;

#pragma unroll
        for (int kk = 0; kk < 128; kk += 16) {
            uint32_t a[4], bfr[8][2];
            ldm_x4(a, sQ + (uint32_t)(a_row * QST + kk + a_koff) * 2);
#pragma unroll
            for (int np = 0; np < 4; np++) {
                uint32_t r4[4];
                ldm_x4(r4, sKb + (uint32_t)((np * 16 + b_row) * KST + kk + b_koff) * 2);
                bfr[np * 2][0] = r4[0]; bfr[np * 2][1] = r4[1];
                bfr[np * 2 + 1][0] = r4[2]; bfr[np * 2 + 1][1] = r4[3];
            }
#pragma unroll
            for (int nt = 0; nt < 8; nt++)
                mma16(s[nt], a, bfr[nt]);
        }

        if (need_mask) {
#pragma unroll
            for (int nt = 0; nt < 8; nt++) {
#pragma unroll
                for (int r = 0; r < 4; r++) {
                    int i = qrow + ((r >= 2) ? 8 : 0);
                    int j = j0 + nt * 8 + (lane & 3) * 2 + (r & 1);
                    float p = ex2f(fmaf(s[nt][r], EXP_C1, EXP_C2));
                    if (j > i || j + (WINDOW - 1) < i) p = 0.f;
                    s[nt][r] = p;
                    if (r < 2) l0 += p; else l1 += p;
                }
            }
        } else {
#pragma unroll
            for (int nt = 0; nt < 8; nt++) {
#pragma unroll
                for (int r = 0; r < 4; r++) {
                    float p = ex2f(fmaf(s[nt][r], EXP_C1, EXP_C2));
                    s[nt][r] = p;
                    if (r < 2) l0 += p; else l1 += p;
                }
            }
        }

        uint32_t pa[4][4];
#pragma unroll
        for (int ks = 0; ks < 4; ks++) {
            pa[ks][0] = h2u(s[2 * ks][0],     s[2 * ks][1]);
            pa[ks][1] = h2u(s[2 * ks][2],     s[2 * ks][3]);
            pa[ks][2] = h2u(s[2 * ks + 1][0], s[2 * ks + 1][1]);
            pa[ks][3] = h2u(s[2 * ks + 1][2], s[2 * ks + 1][3]);
        }

#pragma unroll
        for (int ks = 0; ks < 4; ks++) {
#pragma unroll
            for (int ng = 0; ng < 8; ng++) {
                uint32_t r4[4];
                ldm_x4_trans(r4, sVb + (uint32_t)((ks * 16 + v_krow) * KST + ng * 16 + v_noff) * 2);
                mma16(o[2 * ng],     pa[ks], r4);
                mma16(o[2 * ng + 1], pa[ks], r4 + 2);
            }
        }
    }

    l0 += __shfl_xor_sync(0xffffffffu, l0, 1);
    l0 += __shfl_xor_sync(0xffffffffu, l0, 2);
    l1 += __shfl_xor_sync(0xffffffffu, l1, 1);
    l1 += __shfl_xor_sync(0xffffffffu, l1, 2);
    float inv0 = 1.f / l0, inv1 = 1.f / l1;

    __half* Ob = O + ((size_t)(b * SEQ + q0 + warp * 16 + (lane >> 2))) * DMODEL + h * HDIM;
#pragma unroll
    for (int nt = 0; nt < 16; nt++) {
        int col = nt * 8 + (lane & 3) * 2;
        *(__half2*)&Ob[col] = __floats2half2_rn(o[nt][0] * inv0, o[nt][1] * inv0);
        *(__half2*)&Ob[(size_t)8 * DMODEL + col] = __floats2half2_rn(o[nt][2] * inv1, o[nt][3] * inv1);
    }
}

// ---------------------------------------------------------------------------
// Launch
// ---------------------------------------------------------------------------
extern "C" void kernel_launch(void* const* d_in, const int* in_sizes, int n_in,
                              void* d_out, int out_size) {
    const float* x  = (const float*)d_in[0];
    const float* Wq = (const float*)d_in[1];
    const float* Wk = (const float*)d_in[2];
    const float* Wv = (const float*)d_in[3];
    const float* Wo = (const float*)d_in[4];
    float* out = (float*)d_out;

    void *pQKV, *pAO, *pXH, *pWH;
    cudaGetSymbolAddress(&pQKV, g_QKVh);
    cudaGetSymbolAddress(&pAO,  g_AOh);
    cudaGetSymbolAddress(&pXH,  g_xh);
    cudaGetSymbolAddress(&pWH,  g_Wh);
    __half* xh = (__half*)pXH;
    __half* Wh = (__half*)pWH;
    const size_t DDn = (size_t)DMODEL * DMODEL;

    cudaFuncSetAttribute(gemm_h<__half>, cudaFuncAttributeMaxDynamicSharedMemorySize, GEMM_SMEM);
    cudaFuncSetAttribute(gemm_h<float>,  cudaFuncAttributeMaxDynamicSharedMemorySize, GEMM_SMEM);
    cudaFuncSetAttribute(attn_h, cudaFuncAttributeMaxDynamicSharedMemorySize, ATTN_SMEM_BYTES);

    {
        int n8x = (MROWS * DMODEL) / 8;
        int n8w = (int)(DDn / 8);
        cvt_f16_kernel<<<n8x / 256, 256>>>((const float4*)x, (uint4*)xh, n8x);
        cvt_w4_kernel<<<(4 * n8w) / 256, 256>>>(Wq, Wk, Wv, Wo, Wh, n8w);
    }

    // Fused QKV projection: 128x128 tiles, 2 CTAs/SM
    gemm_h<__half><<<dim3(3 * DMODEL / BN, MROWS / BM), 256, GEMM_SMEM>>>(
        xh, Wh, (__half*)pQKV, MROWS, 3 * DMODEL, DMODEL);

    attn_h<<<dim3(SEQ / 128, NHEAD, BATCH), 256, ATTN_SMEM_BYTES>>>(
        (const __half*)pQKV, (__half*)pAO);

    gemm_h<float><<<dim3(DMODEL / BN, MROWS / BM), 256, GEMM_SMEM>>>(
        (const __half*)pAO, Wh + 3 * DDn, out, MROWS, DMODEL, DMODEL);
}

// round 14
// speedup vs baseline: 1.0737x; 1.0737x over previous
#include <cuda_runtime.h>
#include <cuda_fp16.h>
#include <math.h>
#include <stdint.h>

// Problem constants
#define BATCH 2
#define SEQ   2048
#define DMODEL 2048
#define NHEAD 16
#define HDIM  128
#define MROWS (BATCH*SEQ)          // 4096
#define WINDOW 512
#define SCALE_F 0.08838834764831845f   // 1/sqrt(128)
#define QKV_ST (3*DMODEL)          // fused QKV row stride
// exp(s*SCALE - 3) via ex2: C1 = SCALE*log2e, C2 = -3*log2e
#define EXP_C1 0.12754334f
#define EXP_C2 (-4.32808512f)

// Scratch (device globals; no allocation allowed)
__device__ __align__(16) __half g_QKVh[ (size_t)MROWS * QKV_ST ];
__device__ __align__(16) __half g_AOh [ (size_t)MROWS * DMODEL ];
__device__ __align__(16) __half g_xh  [ (size_t)MROWS * DMODEL ];
__device__ __align__(16) __half g_Wh  [ (size_t)4 * DMODEL * DMODEL ];

// ---------------------------------------------------------------------------
// helpers
// ---------------------------------------------------------------------------
__device__ __forceinline__ uint32_t smem_u32(const void* p) {
    uint32_t a;
    asm("{ .reg .u64 t; cvta.to.shared.u64 t, %1; cvt.u32.u64 %0, t; }" : "=r"(a) : "l"(p));
    return a;
}

__device__ __forceinline__ void cp_async16(uint32_t dst, const void* src) {
    size_t g = __cvta_generic_to_global(src);
    asm volatile("cp.async.cg.shared.global [%0], [%1], 16;\n" :: "r"(dst), "l"(g));
}
#define CP_COMMIT() asm volatile("cp.async.commit_group;\n" ::: "memory")
#define CP_WAIT(n)  asm volatile("cp.async.wait_group %0;\n" :: "n"(n) : "memory")

__device__ __forceinline__ float ex2f(float x) {
    float r;
    asm("ex2.approx.ftz.f32 %0, %1;" : "=f"(r) : "f"(x));
    return r;
}

// fp16 mma m16n8k16, fp32 accumulate
__device__ __forceinline__ void mma16(float* c, const uint32_t* a, const uint32_t* b) {
    asm volatile(
        "mma.sync.aligned.m16n8k16.row.col.f32.f16.f16.f32 "
        "{%0,%1,%2,%3}, {%4,%5,%6,%7}, {%8,%9}, {%0,%1,%2,%3};"
        : "+f"(c[0]), "+f"(c[1]), "+f"(c[2]), "+f"(c[3])
        : "r"(a[0]), "r"(a[1]), "r"(a[2]), "r"(a[3]), "r"(b[0]), "r"(b[1]));
}

__device__ __forceinline__ uint32_t h2u(float x, float y) {
    __half2 h = __floats2half2_rn(x, y);
    return *(uint32_t*)&h;
}

__device__ __forceinline__ void ldm_x4(uint32_t* r, uint32_t addr) {
    asm volatile("ldmatrix.sync.aligned.m8n8.x4.shared.b16 {%0,%1,%2,%3}, [%4];"
        : "=r"(r[0]), "=r"(r[1]), "=r"(r[2]), "=r"(r[3]) : "r"(addr));
}
__device__ __forceinline__ void ldm_x4_trans(uint32_t* r, uint32_t addr) {
    asm volatile("ldmatrix.sync.aligned.m8n8.x4.trans.shared.b16 {%0,%1,%2,%3}, [%4];"
        : "=r"(r[0]), "=r"(r[1]), "=r"(r[2]), "=r"(r[3]) : "r"(addr));
}

__device__ __forceinline__ void store2(float* C, size_t idx, float a, float b) {
    *(float2*)&C[idx] = make_float2(a, b);
}
__device__ __forceinline__ void store2(__half* C, size_t idx, float a, float b) {
    *(__half2*)&C[idx] = __floats2half2_rn(a, b);
}

// ---------------------------------------------------------------------------
// float -> half conversion: 8 floats in / uint4 out per thread
// ---------------------------------------------------------------------------
__global__ __launch_bounds__(256)
void cvt_f16_kernel(const float4* __restrict__ in, uint4* __restrict__ out, int n8) {
    int i = blockIdx.x * blockDim.x + threadIdx.x;
    if (i < n8) {
        float4 v0 = in[2 * i], v1 = in[2 * i + 1];
        uint4 o;
        o.x = h2u(v0.x, v0.y); o.y = h2u(v0.z, v0.w);
        o.z = h2u(v1.x, v1.y); o.w = h2u(v1.z, v1.w);
        out[i] = o;
    }
}

__global__ __launch_bounds__(256)
void cvt_w4_kernel(const float* __restrict__ w0, const float* __restrict__ w1,
                   const float* __restrict__ w2, const float* __restrict__ w3,
                   __half* __restrict__ out, int n8each) {
    int i = blockIdx.x * blockDim.x + threadIdx.x;
    int sel = i / n8each;
    int idx = i - sel * n8each;
    const float4* src = (const float4*)((sel == 0) ? w0 : (sel == 1) ? w1 : (sel == 2) ? w2 : w3);
    float4 v0 = src[2 * idx], v1 = src[2 * idx + 1];
    uint4 o;
    o.x = h2u(v0.x, v0.y); o.y = h2u(v0.z, v0.w);
    o.z = h2u(v1.x, v1.y); o.w = h2u(v1.z, v1.w);
    ((uint4*)(out + (size_t)sel * (8 * (size_t)n8each)))[idx] = o;
}

// ---------------------------------------------------------------------------
// fp16 GEMM: C[M,N] = A[M,K](f16) * Bw[N,K](f16)^T, fp32 accum, OutT output.
// Block 128xBN (192: QKV wave-balanced, DB frags; 256: O-proj).
// BKH=128 halves per stage, stored as TWO 64-half sub-blocks (128B rows,
// SW128 swizzle identical to the proven 64-chunk layout). NSTAGE=2 with
// single-barrier pipeline: WAIT(0) -> sync -> fill(j+1) -> compute(j).
// 8 warps 2x4, warp tile 64 x (BN/4).
// ---------------------------------------------------------------------------
#define BM 128
#define BKH 128
#define A_BYTES (BM*128)                  // 16384 per sub-block

template <typename TO, int BN_, bool DB>
__global__ __launch_bounds__(256, 1)
void gemm_h(const __half* __restrict__ A, const __half* __restrict__ Bw,
            TO* __restrict__ C, int M, int N, int K) {
    constexpr int WN = BN_ / 4;            // warp n-span (48 or 64)
    constexpr int NT = WN / 8;             // n8 tiles per warp (6 or 8)
    constexpr int NB = WN / 16;            // B ldmatrix.x4 per kk (3 or 4)
    constexpr int SUB = (BM + BN_) * 128;  // bytes per 64-half sub-block
    constexpr int STG = 2 * SUB;           // bytes per 128-half stage
    constexpr int BFILL = BN_ / 32;        // B fill iterations per sub-block

    extern __shared__ char dsm[];
    const int tid  = threadIdx.x;
    const int lane = tid & 31;
    const int warp = tid >> 5;
    const int m0 = blockIdx.y * BM;
    const int n0 = blockIdx.x * BN_;
    const int NIT = K / BKH;               // 16

    const uint32_t sbase = (smem_u32(dsm) + 1023) & ~1023u;

    auto fill = [&](int it) {
        uint32_t stg = sbase + (it & 1) * STG;
#pragma unroll
        for (int sub = 0; sub < 2; sub++) {
            uint32_t st = stg + sub * SUB;
            size_t kb = (size_t)it * BKH + sub * 64;
#pragma unroll
            for (int i = 0; i < 4; i++) {
                int id = tid + i * 256;
                int row = id >> 3, c = id & 7;
                uint32_t off = (uint32_t)(row * 128 + c * 16);
                cp_async16(st + (off ^ ((off >> 3) & 0x70)),
                           A + (size_t)(m0 + row) * K + kb + c * 8);
            }
            uint32_t stB = st + A_BYTES;
#pragma unroll
            for (int i = 0; i < BFILL; i++) {
                int id = tid + i * 256;
                int row = id >> 3, c = id & 7;
                uint32_t off = (uint32_t)(row * 128 + c * 16);
                cp_async16(stB + (off ^ ((off >> 3) & 0x70)),
                           Bw + (size_t)(n0 + row) * K + kb + c * 8);
            }
        }
        CP_COMMIT();
    };

    float acc[4][NT][4];
#pragma unroll
    for (int mt = 0; mt < 4; mt++)
#pragma unroll
        for (int nt = 0; nt < NT; nt++)
#pragma unroll
            for (int r = 0; r < 4; r++) acc[mt][nt][r] = 0.f;

    fill(0);

    const int wm = (warp & 1) * 64;
    const int wn = (warp >> 1) * WN;
    const int a_row  = lane & 15;
    const int a_koff = (lane >> 4) * 8;
    const int b_row  = ((lane >> 4) << 3) + (lane & 7);
    const int b_koff = ((lane >> 3) & 1) * 8;

    auto load_a = [&](uint32_t (*a)[4], uint32_t stg, int kk) {
        uint32_t base = stg + (kk >> 6) * SUB;
        int kkl = kk & 63;
#pragma unroll
        for (int mt = 0; mt < 4; mt++) {
            uint32_t off = (uint32_t)((wm + mt * 16 + a_row) * 128 + (kkl + a_koff) * 2);
            ldm_x4(a[mt], base + (off ^ ((off >> 3) & 0x70)));
        }
    };
    auto load_b = [&](uint32_t (*b)[2], uint32_t stg, int kk) {
        uint32_t base = stg + (kk >> 6) * SUB + A_BYTES;
        int kkl = kk & 63;
#pragma unroll
        for (int np = 0; np < NB; np++) {
            uint32_t off = (uint32_t)((wn + np * 16 + b_row) * 128 + (kkl + b_koff) * 2);
            uint32_t r4[4];
            ldm_x4(r4, base + (off ^ ((off >> 3) & 0x70)));
            b[np * 2][0] = r4[0]; b[np * 2][1] = r4[1];
            b[np * 2 + 1][0] = r4[2]; b[np * 2 + 1][1] = r4[3];
        }
    };

    for (int j = 0; j < NIT; j++) {
        CP_WAIT(0);
        __syncthreads();
        if (j + 1 < NIT) fill(j + 1);

        uint32_t stg = sbase + (j & 1) * STG;
        if (DB) {
            uint32_t a[2][4][4], b[2][NT][2];
            load_a(a[0], stg, 0);
            load_b(b[0], stg, 0);
#pragma unroll
            for (int ki = 0; ki < BKH / 16; ki++) {
                const int cur = ki & 1, nxt = cur ^ 1;
                if (ki + 1 < BKH / 16) {
                    load_a(a[nxt], stg, (ki + 1) * 16);
                    load_b(b[nxt], stg, (ki + 1) * 16);
                }
#pragma unroll
                for (int mt = 0; mt < 4; mt++)
#pragma unroll
                    for (int nt = 0; nt < NT; nt++)
                        mma16(acc[mt][nt], a[cur][mt], b[cur][nt]);
            }
        } else {
#pragma unroll
            for (int kk = 0; kk < BKH; kk += 16) {
                uint32_t a[4][4], b[NT][2];
                load_a(a, stg, kk);
                load_b(b, stg, kk);
#pragma unroll
                for (int mt = 0; mt < 4; mt++)
#pragma unroll
                    for (int nt = 0; nt < NT; nt++)
                        mma16(acc[mt][nt], a[mt], b[nt]);
            }
        }
    }

#pragma unroll
    for (int mt = 0; mt < 4; mt++)
#pragma unroll
        for (int nt = 0; nt < NT; nt++) {
            int row = m0 + wm + mt * 16 + (lane >> 2);
            int col = n0 + wn + nt * 8 + (lane & 3) * 2;
            store2(C, (size_t)row * N + col,       acc[mt][nt][0], acc[mt][nt][1]);
            store2(C, (size_t)(row + 8) * N + col, acc[mt][nt][2], acc[mt][nt][3]);
        }
}

#define GEMM_SMEM_192 (2*2*(BM+192)*128 + 1024)   // 164864
#define GEMM_SMEM_256 (2*2*(BM+256)*128 + 1024)   // 197632

// ---------------------------------------------------------------------------
// Windowed flash attention, fp16 mma + ldmatrix (byte-identical to R11).
// ---------------------------------------------------------------------------
#define QST 136
#define KST 136
#define SMQ (128 * QST)
#define SMKV (64 * KST)
#define ATTN_SMEM_BYTES ((SMQ + 4 * SMKV) * 2)   // 104448 B

__global__ __launch_bounds__(256, 2)
void attn_h(const __half* __restrict__ QKV, __half* __restrict__ O) {
    extern __shared__ __half hsm[];
    __half* Qs = hsm;
    __half* Ks = hsm + SMQ;
    __half* Vs = hsm + SMQ + 2 * SMKV;

    const int tid  = threadIdx.x;
    const int lane = tid & 31;
    const int warp = tid >> 5;
    const int qt = blockIdx.x, h = blockIdx.y, b = blockIdx.z;
    const int q0 = qt * 128;

    const uint32_t sQ = smem_u32(Qs);
    const uint32_t sK = smem_u32(Ks);
    const uint32_t sV = smem_u32(Vs);

    const int jmin = (q0 > (WINDOW - 1)) ? (q0 - (WINDOW - 1)) : 0;
    const int t0 = jmin >> 6;
    const int t1 = (q0 + 127) >> 6;

    auto fillKV = [&](int kt) {
        int buf = kt & 1;
        const __half* Kb = QKV + ((size_t)(b * SEQ + kt * 64)) * QKV_ST + DMODEL + h * HDIM;
        const __half* Vb = Kb + DMODEL;
#pragma unroll
        for (int i = 0; i < 4; i++) {
            int id = tid + i * 256;
            int row = id >> 4, c = id & 15;
            uint32_t doff = (uint32_t)(buf * SMKV + row * KST + c * 8) * 2;
            cp_async16(sK + doff, Kb + (size_t)row * QKV_ST + c * 8);
            cp_async16(sV + doff, Vb + (size_t)row * QKV_ST + c * 8);
        }
        CP_COMMIT();
    };

    {
        const __half* Qb = QKV + ((size_t)(b * SEQ + q0)) * QKV_ST + h * HDIM;
#pragma unroll
        for (int i = 0; i < 8; i++) {
            int id = tid + i * 256;
            int row = id >> 4, c = id & 15;
            cp_async16(sQ + (uint32_t)(row * QST + c * 8) * 2,
                       Qb + (size_t)row * QKV_ST + c * 8);
        }
    }
    fillKV(t0);

    float o[16][4];
#pragma unroll
    for (int nt = 0; nt < 16; nt++)
#pragma unroll
        for (int r = 0; r < 4; r++) o[nt][r] = 0.f;
    float l0 = 0.f, l1 = 0.f;

    const int qrow  = q0 + warp * 16 + (lane >> 2);
    const int i_min = q0 + warp * 16;
    const int i_max = i_min + 15;
    const int a_row  = warp * 16 + (lane & 15);
    const int a_koff = (lane >> 4) * 8;
    const int b_row  = ((lane >> 4) << 3) + (lane & 7);
    const int b_koff = ((lane >> 3) & 1) * 8;
    const int v_krow = lane & 15;
    const int v_noff = (lane >> 4) * 8;

    for (int kt = t0; kt <= t1; kt++) {
        const int j0 = kt * 64;
        const int buf = kt & 1;
        CP_WAIT(0);
        __syncthreads();
        if (kt < t1) fillKV(kt + 1);

        const bool dead = (j0 > i_max) || (j0 + 63 + (WINDOW - 1) < i_min);
        if (dead) continue;
        const bool need_mask = (j0 + 63 > i_min) || (j0 < i_max - (WINDOW - 1));

        const uint32_t sKb = sK + (uint32_t)(buf * SMKV) * 2;
        const uint32_t sVb = sV + (uint32_t)(buf * SMKV) * 2;

        float s[8][4];
#pragma unroll
        for (int nt = 0; nt < 8; nt++)
#pragma unroll
            for (int r = 0; r < 4; r++) s[nt][r] = 0.f;

#pragma unroll
        for (int kk = 0; kk < 128; kk += 16) {
            uint32_t a[4], bfr[8][2];
            ldm_x4(a, sQ + (uint32_t)(a_row * QST + kk + a_koff) * 2);
#pragma unroll
            for (int np = 0; np < 4; np++) {
                uint32_t r4[4];
                ldm_x4(r4, sKb + (uint32_t)((np * 16 + b_row) * KST + kk + b_koff) * 2);
                bfr[np * 2][0] = r4[0]; bfr[np * 2][1] = r4[1];
                bfr[np * 2 + 1][0] = r4[2]; bfr[np * 2 + 1][1] = r4[3];
            }
#pragma unroll
            for (int nt = 0; nt < 8; nt++)
                mma16(s[nt], a, bfr[nt]);
        }

        if (need_mask) {
#pragma unroll
            for (int nt = 0; nt < 8; nt++) {
#pragma unroll
                for (int r = 0; r < 4; r++) {
                    int i = qrow + ((r >= 2) ? 8 : 0);
                    int j = j0 + nt * 8 + (lane & 3) * 2 + (r & 1);
                    float p = ex2f(fmaf(s[nt][r], EXP_C1, EXP_C2));
                    if (j > i || j + (WINDOW - 1) < i) p = 0.f;
                    s[nt][r] = p;
                    if (r < 2) l0 += p; else l1 += p;
                }
            }
        } else {
#pragma unroll
            for (int nt = 0; nt < 8; nt++) {
#pragma unroll
                for (int r = 0; r < 4; r++) {
                    float p = ex2f(fmaf(s[nt][r], EXP_C1, EXP_C2));
                    s[nt][r] = p;
                    if (r < 2) l0 += p; else l1 += p;
                }
            }
        }

        uint32_t pa[4][4];
#pragma unroll
        for (int ks = 0; ks < 4; ks++) {
            pa[ks][0] = h2u(s[2 * ks][0],     s[2 * ks][1]);
            pa[ks][1] = h2u(s[2 * ks][2],     s[2 * ks][3]);
            pa[ks][2] = h2u(s[2 * ks + 1][0], s[2 * ks + 1][1]);
            pa[ks][3] = h2u(s[2 * ks + 1][2], s[2 * ks + 1][3]);
        }

#pragma unroll
        for (int ks = 0; ks < 4; ks++) {
#pragma unroll
            for (int ng = 0; ng < 8; ng++) {
                uint32_t r4[4];
                ldm_x4_trans(r4, sVb + (uint32_t)((ks * 16 + v_krow) * KST + ng * 16 + v_noff) * 2);
                mma16(o[2 * ng],     pa[ks], r4);
                mma16(o[2 * ng + 1], pa[ks], r4 + 2);
            }
        }
    }

    l0 += __shfl_xor_sync(0xffffffffu, l0, 1);
    l0 += __shfl_xor_sync(0xffffffffu, l0, 2);
    l1 += __shfl_xor_sync(0xffffffffu, l1, 1);
    l1 += __shfl_xor_sync(0xffffffffu, l1, 2);
    float inv0 = 1.f / l0, inv1 = 1.f / l1;

    __half* Ob = O + ((size_t)(b * SEQ + q0 + warp * 16 + (lane >> 2))) * DMODEL + h * HDIM;
#pragma unroll
    for (int nt = 0; nt < 16; nt++) {
        int col = nt * 8 + (lane & 3) * 2;
        *(__half2*)&Ob[col] = __floats2half2_rn(o[nt][0] * inv0, o[nt][1] * inv0);
        *(__half2*)&Ob[(size_t)8 * DMODEL + col] = __floats2half2_rn(o[nt][2] * inv1, o[nt][3] * inv1);
    }
}

// ---------------------------------------------------------------------------
// Launch
// ---------------------------------------------------------------------------
extern "C" void kernel_launch(void* const* d_in, const int* in_sizes, int n_in,
                              void* d_out, int out_size) {
    const float* x  = (const float*)d_in[0];
    const float* Wq = (const float*)d_in[1];
    const float* Wk = (const float*)d_in[2];
    const float* Wv = (const float*)d_in[3];
    const float* Wo = (const float*)d_in[4];
    float* out = (float*)d_out;

    void *pQKV, *pAO, *pXH, *pWH;
    cudaGetSymbolAddress(&pQKV, g_QKVh);
    cudaGetSymbolAddress(&pAO,  g_AOh);
    cudaGetSymbolAddress(&pXH,  g_xh);
    cudaGetSymbolAddress(&pWH,  g_Wh);
    __half* xh = (__half*)pXH;
    __half* Wh = (__half*)pWH;
    const size_t DDn = (size_t)DMODEL * DMODEL;

    cudaFuncSetAttribute((gemm_h<__half, 192, true>),
                         cudaFuncAttributeMaxDynamicSharedMemorySize, GEMM_SMEM_192);
    cudaFuncSetAttribute((gemm_h<float, 256, false>),
                         cudaFuncAttributeMaxDynamicSharedMemorySize, GEMM_SMEM_256);
    cudaFuncSetAttribute(attn_h, cudaFuncAttributeMaxDynamicSharedMemorySize, ATTN_SMEM_BYTES);

    {
        int n8x = (MROWS * DMODEL) / 8;
        int n8w = (int)(DDn / 8);
        cvt_f16_kernel<<<n8x / 256, 256>>>((const float4*)x, (uint4*)xh, n8x);
        cvt_w4_kernel<<<(4 * n8w) / 256, 256>>>(Wq, Wk, Wv, Wo, Wh, n8w);
    }

    // Fused QKV projection, 128x192 tiles: grid 32x32 = 1024 CTAs
    gemm_h<__half, 192, true><<<dim3(3 * DMODEL / 192, MROWS / BM), 256, GEMM_SMEM_192>>>(
        xh, Wh, (__half*)pQKV, MROWS, 3 * DMODEL, DMODEL);

    attn_h<<<dim3(SEQ / 128, NHEAD, BATCH), 256, ATTN_SMEM_BYTES>>>(
        (const __half*)pQKV, (__half*)pAO);

    gemm_h<float, 256, false><<<dim3(DMODEL / 256, MROWS / BM), 256, GEMM_SMEM_256>>>(
        (const __half*)pAO, Wh + 3 * DDn, out, MROWS, DMODEL, DMODEL);
}